// round 5
// baseline (speedup 1.0000x reference)
#include <cuda_runtime.h>
#include <cstddef>

#define NN   8192
#define FIN  512
#define HID  128
#define NCLS 16
#define CAP  256

static __device__ __constant__ float C_RES  = 0.5555555555555556f;  // 1/(1+0.8)
static __device__ __constant__ float C_PROP = 0.4444444444444444f;  // 0.8/(1+0.8)

// ---- scratch (device globals; no allocation allowed) ----
__device__ int   g_col[NN * CAP];
__device__ float g_val[NN * CAP];
__device__ int   g_cnt[NN];
__device__ float g_dinv[NN];
__device__ float g_h1[NN * HID];
__device__ float g_bufA[NN * HID];
__device__ float g_bufB[NN * HID];
__device__ float g_h2[NN * NCLS];
__device__ float g_cA[NN * NCLS];
__device__ float g_cB[NN * NCLS];

// ---------------------------------------------------------------------------
// 1) Extract sparse structure of (A + I): one warp per row, ordered ballot
//    compaction (fully deterministic). Also computes deg and dinv = rsqrt(deg).
// ---------------------------------------------------------------------------
__global__ __launch_bounds__(512) void k_extract(const float* __restrict__ adj) {
    int warp = blockIdx.x * (blockDim.x >> 5) + (threadIdx.x >> 5);
    int lane = threadIdx.x & 31;
    if (warp >= NN) return;
    const float* row = adj + (size_t)warp * NN;
    int base = warp * CAP;
    int cnt = 0;
    float deg = 0.0f;
    for (int c0 = 0; c0 < NN; c0 += 32) {
        int c = c0 + lane;
        float v = __ldcs(&row[c]);
        if (c == warp) v += 1.0f;          // self loop
        deg += v;
        unsigned m = __ballot_sync(0xffffffffu, v != 0.0f);
        if (v != 0.0f) {
            int pos = base + cnt + __popc(m & ((1u << lane) - 1u));
            if (pos < base + CAP) { g_col[pos] = c; g_val[pos] = v; }
        }
        cnt += __popc(m);
    }
#pragma unroll
    for (int o = 16; o > 0; o >>= 1) deg += __shfl_xor_sync(0xffffffffu, deg, o);
    if (lane == 0) {
        g_cnt[warp]  = cnt < CAP ? cnt : CAP;
        g_dinv[warp] = rsqrtf(deg);        // deg >= 1 always (self loop)
    }
}

// ---------------------------------------------------------------------------
// 2) val(i,j) *= dinv[i]*dinv[j]  (symmetric normalization folded into values)
// ---------------------------------------------------------------------------
__global__ __launch_bounds__(128) void k_scale() {
    int i = blockIdx.x;
    int cnt = g_cnt[i];
    float di = g_dinv[i];
    int base = i * CAP;
    for (int t = threadIdx.x; t < cnt; t += blockDim.x) {
        g_val[base + t] *= di * g_dinv[g_col[base + t]];
    }
}

// ---------------------------------------------------------------------------
// 3) h1 = x @ W1   (8192x512 @ 512x128).  16 rows x 128 cols per block.
// ---------------------------------------------------------------------------
__global__ __launch_bounds__(128) void k_gemm1(const float* __restrict__ x,
                                               const float* __restrict__ W1) {
    __shared__ float xs[16 * FIN];
    int r0 = blockIdx.x * 16;
    int f  = threadIdx.x;   // 0..127 (output column)
    const float4* src = (const float4*)(x + (size_t)r0 * FIN);
    float4* dstv = (float4*)xs;
    for (int t = f; t < 16 * FIN / 4; t += blockDim.x) dstv[t] = src[t];
    __syncthreads();
    float acc[16];
#pragma unroll
    for (int r = 0; r < 16; r++) acc[r] = 0.0f;
#pragma unroll 4
    for (int k = 0; k < FIN; k++) {
        float w = __ldg(&W1[k * HID + f]);
#pragma unroll
        for (int r = 0; r < 16; r++) acc[r] = fmaf(xs[r * FIN + k], w, acc[r]);
    }
#pragma unroll
    for (int r = 0; r < 16; r++) g_h1[(size_t)(r0 + r) * HID + f] = acc[r];
}

// ---------------------------------------------------------------------------
// 4) SpMM width 128: one warp per row, float4 per lane (512B coalesced gathers)
//    dst = C_PROP * (An @ src) + C_RES * h1
// ---------------------------------------------------------------------------
__global__ __launch_bounds__(256) void k_spmm128(int s) {
    int row  = blockIdx.x * 8 + (threadIdx.x >> 5);
    int lane = threadIdx.x & 31;
    const float4* src = (const float4*)((s == 0) ? g_h1 : ((s & 1) ? g_bufA : g_bufB));
    float4* dst = (float4*)((s & 1) ? g_bufB : g_bufA);
    int cnt = g_cnt[row];
    int base = row * CAP;
    float ax = 0.f, ay = 0.f, az = 0.f, aw = 0.f;
    int k = 0;
    for (; k + 4 <= cnt; k += 4) {
#pragma unroll
        for (int u = 0; u < 4; u++) {
            int   c = __ldg(&g_col[base + k + u]);
            float v = __ldg(&g_val[base + k + u]);
            float4 d = src[(size_t)c * 32 + lane];
            ax = fmaf(v, d.x, ax); ay = fmaf(v, d.y, ay);
            az = fmaf(v, d.z, az); aw = fmaf(v, d.w, aw);
        }
    }
    for (; k < cnt; k++) {
        int   c = __ldg(&g_col[base + k]);
        float v = __ldg(&g_val[base + k]);
        float4 d = src[(size_t)c * 32 + lane];
        ax = fmaf(v, d.x, ax); ay = fmaf(v, d.y, ay);
        az = fmaf(v, d.z, az); aw = fmaf(v, d.w, aw);
    }
    float4 h = ((const float4*)g_h1)[(size_t)row * 32 + lane];
    float4 o;
    o.x = C_PROP * ax + C_RES * h.x;
    o.y = C_PROP * ay + C_RES * h.y;
    o.z = C_PROP * az + C_RES * h.z;
    o.w = C_PROP * aw + C_RES * h.w;
    dst[(size_t)row * 32 + lane] = o;
}

// ---------------------------------------------------------------------------
// 5) h2 = relu(diffused1 + b1) @ W2   (8192x128 @ 128x16), thread per (row,c)
// ---------------------------------------------------------------------------
__global__ __launch_bounds__(128) void k_gemm2(const float* __restrict__ W2,
                                               const float* __restrict__ b1) {
    int idx = blockIdx.x * blockDim.x + threadIdx.x;   // 0..131071
    int row = idx >> 4;
    int c   = idx & 15;
    const float* src = g_bufB + (size_t)row * HID;     // 8 steps end in bufB
    float acc = 0.0f;
#pragma unroll 4
    for (int k = 0; k < HID; k++) {
        float hv = fmaxf(src[k] + __ldg(&b1[k]), 0.0f);
        acc = fmaf(hv, __ldg(&W2[k * NCLS + c]), acc);
    }
    g_h2[idx] = acc;
}

// ---------------------------------------------------------------------------
// 6) SpMM width 16: 4 threads per row, float4 per thread
// ---------------------------------------------------------------------------
__global__ __launch_bounds__(256) void k_spmm16(int s) {
    int tid = blockIdx.x * blockDim.x + threadIdx.x;
    int row = tid >> 2;
    int q   = tid & 3;
    const float4* src = (const float4*)((s == 0) ? g_h2 : ((s & 1) ? g_cA : g_cB));
    float4* dst = (float4*)((s & 1) ? g_cB : g_cA);
    int cnt = g_cnt[row];
    int base = row * CAP;
    float ax = 0.f, ay = 0.f, az = 0.f, aw = 0.f;
    for (int k = 0; k < cnt; k++) {
        int   c = __ldg(&g_col[base + k]);
        float v = __ldg(&g_val[base + k]);
        float4 d = src[(size_t)c * 4 + q];
        ax = fmaf(v, d.x, ax); ay = fmaf(v, d.y, ay);
        az = fmaf(v, d.z, az); aw = fmaf(v, d.w, aw);
    }
    float4 h = ((const float4*)g_h2)[(size_t)row * 4 + q];
    float4 o;
    o.x = C_PROP * ax + C_RES * h.x;
    o.y = C_PROP * ay + C_RES * h.y;
    o.z = C_PROP * az + C_RES * h.z;
    o.w = C_PROP * aw + C_RES * h.w;
    dst[(size_t)row * 4 + q] = o;
}

// ---------------------------------------------------------------------------
// 7) out = log_softmax(diffused2 + b2, axis=1)
// ---------------------------------------------------------------------------
__global__ __launch_bounds__(256) void k_final(const float* __restrict__ b2,
                                               float* __restrict__ out) {
    int row = blockIdx.x * blockDim.x + threadIdx.x;
    if (row >= NN) return;
    float v[NCLS];
    float mx = -1e30f;
#pragma unroll
    for (int c = 0; c < NCLS; c++) {
        v[c] = g_cB[(size_t)row * NCLS + c] + __ldg(&b2[c]);   // 8 steps end in cB
        mx = fmaxf(mx, v[c]);
    }
    float sum = 0.0f;
#pragma unroll
    for (int c = 0; c < NCLS; c++) sum += expf(v[c] - mx);
    float lse = mx + logf(sum);
#pragma unroll
    for (int c = 0; c < NCLS; c++) out[(size_t)row * NCLS + c] = v[c] - lse;
}

// ---------------------------------------------------------------------------
extern "C" void kernel_launch(void* const* d_in, const int* in_sizes, int n_in,
                              void* d_out, int out_size) {
    const float* x   = (const float*)d_in[0];
    const float* adj = (const float*)d_in[1];
    const float* W1  = (const float*)d_in[2];
    const float* b1  = (const float*)d_in[3];
    const float* W2  = (const float*)d_in[4];
    const float* b2  = (const float*)d_in[5];
    float* out = (float*)d_out;

    k_extract<<<NN / 16, 512>>>(adj);
    k_scale<<<NN, 128>>>();
    k_gemm1<<<NN / 16, 128>>>(x, W1);
    for (int s = 0; s < 8; s++) k_spmm128<<<NN / 8, 256>>>(s);
    k_gemm2<<<(NN * NCLS) / 128, 128>>>(W2, b1);
    for (int s = 0; s < 8; s++) k_spmm16<<<(NN * 4) / 256, 256>>>(s);
    k_final<<<NN / 256, 256>>>(b2, out);
}